// round 9
// baseline (speedup 1.0000x reference)
#include <cuda_runtime.h>

// DecisionTree: out[b, j] = prod_f softmax((x[b,f]*W + cumsum_bias[f]) / 0.1)[digit_f(j)]
// out = (4096, 16384) fp32 = 256 MiB. Store-bound (~7.1 TB/s effective writes).
// R9: R2 shape (grid 16384 = 4 CTAs/row, 16 KB/CTA) but with Blackwell 256-bit
//     stores (st.global.cs.v8.f32): 2 stores of 32 B per thread, halving L1tex
//     store wavefronts vs 4x STG.128.

#define FF 7
#define SEGS 4                      // CTAs per row
#define ROW_SCALARS 16384

__global__ __launch_bounds__(256, 8)
void dt_kernel(const float* __restrict__ x,
               const float* __restrict__ cut,
               float* __restrict__ out) {
    __shared__ float bins[FF][4];

    const int bid = blockIdx.x;
    const int row = bid >> 2;       // bid / SEGS
    const int seg = bid & 3;        // bid % SEGS  (= digit d0)
    const int t   = threadIdx.x;

    // --- per-feature softmax bins (threads 0..6) ---
    if (t < FF) {
        float c0 = cut[t * 3 + 0];
        float c1 = cut[t * 3 + 1];
        float c2 = cut[t * 3 + 2];
        // sort 3 values ascending
        float lo = fminf(c0, c1), hi = fmaxf(c0, c1);
        float s0 = fminf(lo, c2);
        float s2 = fmaxf(hi, c2);
        float s1 = (c0 + c1 + c2) - s0 - s2;
        // cumulative biases: b0=0, b1=-s0, b2=-s0-s1, b3=-s0-s1-s2
        float b1 = -s0;
        float b2 = b1 - s1;
        float b3 = b2 - s2;

        float xv = x[row * FF + t];
        float h0 = xv * 10.0f;
        float h1 = (xv * 2.0f + b1) * 10.0f;
        float h2 = (xv * 3.0f + b2) * 10.0f;
        float h3 = (xv * 4.0f + b3) * 10.0f;
        float m  = fmaxf(fmaxf(h0, h1), fmaxf(h2, h3));
        float e0 = __expf(h0 - m);
        float e1 = __expf(h1 - m);
        float e2 = __expf(h2 - m);
        float e3 = __expf(h3 - m);
        float inv = 1.0f / (e0 + e1 + e2 + e3);
        bins[t][0] = e0 * inv;
        bins[t][1] = e1 * inv;
        bins[t][2] = e2 * inv;
        bins[t][3] = e3 * inv;
    }
    __syncthreads();

    // Segment-local scalar offset s = iter*2048 + t*8 + e, e in [0,8).
    // Digits: d0=seg, d1=iter*2+(t>>7), d2=(t>>5)&3, d3=(t>>3)&3, d4=(t>>1)&3,
    //         d5=(t&1)*2+(e>>2), d6=e&3.
    float p234 = bins[2][(t >> 5) & 3] * bins[3][(t >> 3) & 3] * bins[4][(t >> 1) & 3];
    float p0   = bins[0][seg];

    // feature-6 row and the two d5 values this thread covers
    float f60 = bins[6][0], f61 = bins[6][1], f62 = bins[6][2], f63 = bins[6][3];
    float d5a = bins[5][(t & 1) * 2];       // e < 4
    float d5b = bins[5][(t & 1) * 2 + 1];   // e >= 4

    float base = p0 * p234;
    float pa = base * d5a;   // still missing bins[1][d1]
    float pb = base * d5b;

    float* gp = out + (size_t)row * ROW_SCALARS + seg * 4096 + t * 8;

#pragma unroll
    for (int iter = 0; iter < 2; iter++) {
        int d1 = iter * 2 + (t >> 7);
        float b1v = bins[1][d1];
        float qa = pa * b1v;
        float qb = pb * b1v;
        float v0 = qa * f60, v1 = qa * f61, v2 = qa * f62, v3 = qa * f63;
        float v4 = qb * f60, v5 = qb * f61, v6 = qb * f62, v7 = qb * f63;
        asm volatile(
            "st.global.cs.v8.f32 [%0], {%1,%2,%3,%4,%5,%6,%7,%8};"
            :: "l"(gp + iter * 2048),
               "f"(v0), "f"(v1), "f"(v2), "f"(v3),
               "f"(v4), "f"(v5), "f"(v6), "f"(v7)
            : "memory");
    }
}

extern "C" void kernel_launch(void* const* d_in, const int* in_sizes, int n_in,
                              void* d_out, int out_size) {
    const float* x   = (const float*)d_in[0];        // (4096, 7)
    const float* cut = (const float*)d_in[1];        // (7, 3)
    float* out = (float*)d_out;                      // (4096, 16384)
    dt_kernel<<<4096 * SEGS, 256>>>(x, cut, out);
}